// round 5
// baseline (speedup 1.0000x reference)
#include <cuda_runtime.h>
#include <cuda_bf16.h>
#include <cstdint>
#include <cfloat>

// Problem shape (fixed by the dataset)
#define B_ROWS 4096
#define N_ROWS 32768
#define DIM    512

#define NSLICES 16
#define SLICE_N (N_ROWS / NSLICES)      // 2048
#define BM 128
#define BN 128
#define BK 32
#define KTILES (DIM / BK)               // 16
#define MTILES (B_ROWS / BM)            // 32
#define NT_PER_SLICE (SLICE_N / BN)     // 16
#define TOPK_CAP 10
#define LDS_A 40                        // padded smem row stride (bf16 elems) = 80B

// ---- device scratch (no cudaMalloc allowed) ----
__device__ __nv_bfloat16 g_Xb[(size_t)B_ROWS * DIM];
__device__ __nv_bfloat16 g_Yb[(size_t)B_ROWS * DIM];
__device__ __nv_bfloat16 g_Zt[(size_t)N_ROWS * DIM];
__device__ __nv_bfloat16 g_Zr[(size_t)N_ROWS * DIM];
__device__ float g_top[(size_t)2 * B_ROWS * NSLICES * TOPK_CAP];
__device__ float g_acc[3];   // [0]=dot(X_trans,Y_tgt)  [1]=fk0 sum  [2]=fk1 sum

// ---- PTX helpers ----
__device__ __forceinline__ uint32_t smem_u32(const void* p) {
    return (uint32_t)__cvta_generic_to_shared(p);
}
__device__ __forceinline__ void cp_async16(uint32_t dst, const void* src) {
    asm volatile("cp.async.cg.shared.global [%0], [%1], 16;\n" :: "r"(dst), "l"(src));
}
__device__ __forceinline__ void ldm_x4(uint32_t& r0, uint32_t& r1, uint32_t& r2, uint32_t& r3,
                                       uint32_t addr) {
    asm volatile("ldmatrix.sync.aligned.m8n8.x4.shared.b16 {%0,%1,%2,%3}, [%4];\n"
                 : "=r"(r0), "=r"(r1), "=r"(r2), "=r"(r3) : "r"(addr));
}
__device__ __forceinline__ void mma_bf16(float* c, const uint32_t* a, const uint32_t* b) {
    asm volatile(
        "mma.sync.aligned.m16n8k16.row.col.f32.bf16.bf16.f32 "
        "{%0,%1,%2,%3}, {%4,%5,%6,%7}, {%8,%9}, {%0,%1,%2,%3};\n"
        : "+f"(c[0]), "+f"(c[1]), "+f"(c[2]), "+f"(c[3])
        : "r"(a[0]), "r"(a[1]), "r"(a[2]), "r"(a[3]), "r"(b[0]), "r"(b[1]));
}

// ---- tiny kernels ----
__global__ void zero_kernel() {
    if (threadIdx.x < 3) g_acc[threadIdx.x] = 0.0f;
}

__global__ void prep_kernel(const float* __restrict__ Xt, const float* __restrict__ Yt,
                            const float* __restrict__ Zt, const float* __restrict__ Zr) {
    size_t stride = (size_t)gridDim.x * blockDim.x;
    size_t i0 = (size_t)blockIdx.x * blockDim.x + threadIdx.x;
    const size_t nB = (size_t)B_ROWS * DIM;
    const size_t nN = (size_t)N_ROWS * DIM;
    for (size_t i = i0; i < nB; i += stride) {
        g_Xb[i] = __float2bfloat16(Xt[i]);
        g_Yb[i] = __float2bfloat16(Yt[i]);
    }
    for (size_t i = i0; i < nN; i += stride) {
        g_Zt[i] = __float2bfloat16(Zt[i]);
        g_Zr[i] = __float2bfloat16(Zr[i]);
    }
}

__global__ void dot_kernel(const float* __restrict__ X, const float* __restrict__ Y) {
    float s = 0.0f;
    size_t stride = (size_t)gridDim.x * blockDim.x;
    for (size_t i = (size_t)blockIdx.x * blockDim.x + threadIdx.x;
         i < (size_t)B_ROWS * DIM; i += stride)
        s += X[i] * Y[i];
    #pragma unroll
    for (int o = 16; o; o >>= 1) s += __shfl_xor_sync(0xFFFFFFFFu, s, o);
    __shared__ float ws[8];
    if ((threadIdx.x & 31) == 0) ws[threadIdx.x >> 5] = s;
    __syncthreads();
    if (threadIdx.x < 8) {
        float v = ws[threadIdx.x];
        #pragma unroll
        for (int o = 4; o; o >>= 1) v += __shfl_xor_sync(0xFFu, v, o);
        if (threadIdx.x == 0) atomicAdd(&g_acc[0], v);
    }
}

// ---- fused bf16 GEMM (A[BM,K] @ Z[BN,K]^T) + per-row streaming top-10 ----
// grid: x = MTILES*NSLICES, y = 2 (matrix pair select); block: 256 threads (8 warps, 4x2)
__global__ void __launch_bounds__(256) gemm_topk_kernel() {
    __shared__ __align__(16) char smem[40960];
    __nv_bfloat16* sAb = (__nv_bfloat16*)smem;                         // 2 bufs * 128*40
    __nv_bfloat16* sBb = (__nv_bfloat16*)(smem + 2 * BM * LDS_A * 2);  // 2 bufs * 128*40
    float* sScore = (float*)smem;   // aliased over tile buffers, used between tiles (64x132)

    const int mat = blockIdx.y;
    const __nv_bfloat16* __restrict__ Amat = mat ? g_Yb : g_Xb;
    const __nv_bfloat16* __restrict__ Zmat = mat ? g_Zr : g_Zt;
    const int mblk  = blockIdx.x % MTILES;
    const int slice = blockIdx.x / MTILES;
    const int m0    = mblk * BM;
    const int nbase = slice * SLICE_N;

    const int tid = threadIdx.x;
    const int lane = tid & 31, wid = tid >> 5;
    const int warpM = wid >> 1, warpN = wid & 1;

    const uint32_t sA_u = smem_u32(sAb);
    const uint32_t sB_u = smem_u32(sBb);

    // per-owner-thread top-10 state (thread t owns row m0+t, t<128)
    float top[TOPK_CAP];
    float thr = -FLT_MAX;
    int minIdx = 0;
    #pragma unroll
    for (int i = 0; i < TOPK_CAP; ++i) top[i] = -FLT_MAX;

    // cp.async mapping: 512 x 16B segments per 128x32 tile; 2 per thread per matrix
    const int s0 = tid, s1 = tid + 256;
    const int lr0 = s0 >> 2, lc0 = (s0 & 3) * 8;
    const int lr1 = s1 >> 2, lc1 = (s1 & 3) * 8;

    const int g = lane >> 2, tig = lane & 3;

    for (int nt = 0; nt < NT_PER_SLICE; ++nt) {
        const int n0 = nbase + nt * BN;
        float acc[2][8][4];
        #pragma unroll
        for (int a = 0; a < 2; ++a)
            #pragma unroll
            for (int b = 0; b < 8; ++b)
                #pragma unroll
                for (int c = 0; c < 4; ++c) acc[a][b][c] = 0.0f;

        auto issue = [&](int kt, int buf) {
            const uint32_t base = (uint32_t)buf * (BM * LDS_A * 2);
            cp_async16(sA_u + base + (lr0 * LDS_A + lc0) * 2,
                       Amat + (size_t)(m0 + lr0) * DIM + kt * BK + lc0);
            cp_async16(sA_u + base + (lr1 * LDS_A + lc1) * 2,
                       Amat + (size_t)(m0 + lr1) * DIM + kt * BK + lc1);
            cp_async16(sB_u + base + (lr0 * LDS_A + lc0) * 2,
                       Zmat + (size_t)(n0 + lr0) * DIM + kt * BK + lc0);
            cp_async16(sB_u + base + (lr1 * LDS_A + lc1) * 2,
                       Zmat + (size_t)(n0 + lr1) * DIM + kt * BK + lc1);
            asm volatile("cp.async.commit_group;\n");
        };

        issue(0, 0);
        for (int kt = 0; kt < KTILES; ++kt) {
            const int cur = kt & 1;
            if (kt + 1 < KTILES) {
                issue(kt + 1, cur ^ 1);
                asm volatile("cp.async.wait_group 1;\n" ::: "memory");
            } else {
                asm volatile("cp.async.wait_group 0;\n" ::: "memory");
            }
            __syncthreads();

            const uint32_t abase = sA_u + (uint32_t)cur * (BM * LDS_A * 2);
            const uint32_t bbase = sB_u + (uint32_t)cur * (BM * LDS_A * 2);
            #pragma unroll
            for (int ks = 0; ks < 2; ++ks) {
                uint32_t afr[2][4];
                #pragma unroll
                for (int mf = 0; mf < 2; ++mf) {
                    int row = warpM * 32 + mf * 16 + ((lane >> 3) & 1) * 8 + (lane & 7);
                    int col = ks * 16 + ((lane >> 4) & 1) * 8;
                    ldm_x4(afr[mf][0], afr[mf][1], afr[mf][2], afr[mf][3],
                           abase + (row * LDS_A + col) * 2);
                }
                uint32_t bfr[8][2];
                #pragma unroll
                for (int p = 0; p < 4; ++p) {
                    int row = warpN * 64 + p * 16 + ((lane >> 4) & 1) * 8 + (lane & 7);
                    int col = ks * 16 + ((lane >> 3) & 1) * 8;
                    uint32_t r0, r1, r2, r3;
                    ldm_x4(r0, r1, r2, r3, bbase + (row * LDS_A + col) * 2);
                    bfr[2 * p][0] = r0;     bfr[2 * p][1] = r1;
                    bfr[2 * p + 1][0] = r2; bfr[2 * p + 1][1] = r3;
                }
                #pragma unroll
                for (int mf = 0; mf < 2; ++mf)
                    #pragma unroll
                    for (int nf = 0; nf < 8; ++nf)
                        mma_bf16(acc[mf][nf], afr[mf], bfr[nf]);
            }
            __syncthreads();
        }

        // Epilogue: dump scores into (aliased) smem 64 rows at a time,
        // owner threads stream them into their private top-10.
        #pragma unroll
        for (int h = 0; h < 2; ++h) {
            if ((warpM >> 1) == h) {
                #pragma unroll
                for (int mf = 0; mf < 2; ++mf) {
                    int r0 = (warpM & 1) * 32 + mf * 16 + g;
                    #pragma unroll
                    for (int nf = 0; nf < 8; ++nf) {
                        int c = warpN * 64 + nf * 8 + tig * 2;
                        *(float2*)&sScore[r0 * 132 + c] =
                            make_float2(acc[mf][nf][0], acc[mf][nf][1]);
                        *(float2*)&sScore[(r0 + 8) * 132 + c] =
                            make_float2(acc[mf][nf][2], acc[mf][nf][3]);
                    }
                }
            }
            __syncthreads();
            if (tid < 128 && (tid >> 6) == h) {
                int lr = tid & 63;
                #pragma unroll 4
                for (int j = 0; j < BN; ++j) {
                    float v = sScore[lr * 132 + j];
                    if (v > thr) {
                        top[minIdx] = v;
                        thr = top[0]; minIdx = 0;
                        #pragma unroll
                        for (int i = 1; i < TOPK_CAP; ++i)
                            if (top[i] < thr) { thr = top[i]; minIdx = i; }
                    }
                }
            }
            __syncthreads();
        }
    }

    if (tid < BM) {
        size_t base = (((size_t)mat * B_ROWS + (size_t)(m0 + tid)) * NSLICES + slice) * TOPK_CAP;
        #pragma unroll
        for (int i = 0; i < TOPK_CAP; ++i) g_top[base + i] = top[i];
    }
}

// merge per-slice top-10s into global top-k per row, sum, reduce
__global__ void merge_kernel(const int* __restrict__ knn) {
    int t = blockIdx.x * blockDim.x + threadIdx.x;
    if (t >= 2 * B_ROWS) return;
    int k = *knn;
    if (k > TOPK_CAP) k = TOPK_CAP;
    if (k < 1) k = 1;
    const float* src = g_top + (size_t)t * NSLICES * TOPK_CAP;
    float best[TOPK_CAP];
    #pragma unroll
    for (int i = 0; i < TOPK_CAP; ++i) best[i] = -FLT_MAX;
    float thr = -FLT_MAX;
    int mi = 0;
    for (int j = 0; j < NSLICES * TOPK_CAP; ++j) {
        float v = src[j];
        if (v > thr) {
            best[mi] = v;
            thr = best[0]; mi = 0;
            for (int i = 1; i < k; ++i)
                if (best[i] < thr) { thr = best[i]; mi = i; }
        }
    }
    float s = 0.0f;
    for (int i = 0; i < k; ++i) s += best[i];
    int mat = t / B_ROWS;
    atomicAdd(&g_acc[1 + mat], s);
}

__global__ void final_kernel(float* __restrict__ out, const int* __restrict__ knn) {
    int k = *knn;
    if (k > TOPK_CAP) k = TOPK_CAP;
    if (k < 1) k = 1;
    // f = 2*dot - fk0 - fk1 ; out = -f/B = (fk0 + fk1 - 2*dot)/B
    out[0] = ((g_acc[1] + g_acc[2]) / (float)k - 2.0f * g_acc[0]) / (float)B_ROWS;
}

extern "C" void kernel_launch(void* const* d_in, const int* in_sizes, int n_in,
                              void* d_out, int out_size) {
    (void)in_sizes; (void)n_in; (void)out_size;
    // metadata order: X_src, X_trans, Y_tgt, Z_src, Z_trans, Z_tgt, knn
    const float* Xt = (const float*)d_in[1];
    const float* Yt = (const float*)d_in[2];
    const float* Zr = (const float*)d_in[4];
    const float* Zt = (const float*)d_in[5];
    const int* knn  = (const int*)d_in[6];
    float* out = (float*)d_out;

    zero_kernel<<<1, 32>>>();
    prep_kernel<<<2048, 256>>>(Xt, Yt, Zt, Zr);
    dot_kernel<<<1024, 256>>>(Xt, Yt);
    dim3 grid(MTILES * NSLICES, 2);
    gemm_topk_kernel<<<grid, 256>>>();
    merge_kernel<<<(2 * B_ROWS + 255) / 256, 256>>>(knn);
    final_kernel<<<1, 1>>>(out, knn);
}